// round 10
// baseline (speedup 1.0000x reference)
#include <cuda_runtime.h>
#include <math.h>

#define LD 65  // padded row stride for 64x64 tiles in smem

// ---------------- intermediates (device globals; no allocation allowed) -----------
__device__ float g_Mp0[64 * 64];
__device__ float g_m1[64 * 512];
__device__ float g_m2[64 * 512];
__device__ float g_u1[64 * 512];
__device__ float g_u2[64 * 512];
__device__ float g_e1[64 * 512];
__device__ float g_e2[64 * 512];
__device__ float g_P[64 * 64];   // P[a,b] = e1[b] . e2[a]

__device__ __forceinline__ float warpSum(float v) {
#pragma unroll
    for (int o = 16; o; o >>= 1) v += __shfl_xor_sync(0xffffffffu, v, o);
    return v;
}
__device__ __forceinline__ float warpMax(float v) {
#pragma unroll
    for (int o = 16; o; o >>= 1) v = fmaxf(v, __shfl_xor_sync(0xffffffffu, v, o));
    return v;
}
__device__ __forceinline__ float dual16(float v) {
#pragma unroll
    for (int o = 8; o; o >>= 1) v += __shfl_xor_sync(0xffffffffu, v, o);
    return v;
}

// ---------------- Mp0 = feat_tra @ feat_det^T + iou : warp per output -------------
__global__ void k_mp0(const float* __restrict__ tra, const float* __restrict__ det,
                      const float* __restrict__ iou) {
    int gw = blockIdx.x * 32 + (threadIdx.x >> 5);
    int lane = threadIdx.x & 31;
    int i = gw >> 6, j = gw & 63;
    const float* a = tra + i * 512;
    const float* b = det + j * 512;
    float s = 0.f;
#pragma unroll 4
    for (int k = lane; k < 512; k += 32) s += a[k] * b[k];
    s = warpSum(s);
    if (!lane) g_Mp0[i * 64 + j] = s + iou[i * 64 + j];
}

// ---------------- m1 = Mp0 @ det, m2 = Mp0^T @ tra --------------------------------
__global__ void k_m12(const float* __restrict__ tra, const float* __restrict__ det) {
    int t = blockIdx.x * blockDim.x + threadIdx.x;
    if (t < 32768) {
        int i = t >> 9, k = t & 511;
        float s = 0.f;
#pragma unroll 8
        for (int j = 0; j < 64; j++) s += g_Mp0[i * 64 + j] * det[j * 512 + k];
        g_m1[t] = s;
    } else {
        int t2 = t - 32768;
        int j = t2 >> 9, k = t2 & 511;
        float s = 0.f;
#pragma unroll 8
        for (int i = 0; i < 64; i++) s += g_Mp0[i * 64 + j] * tra[i * 512 + k];
        g_m2[t2] = s;
    }
}

// ---------------- u = feat + lam * m ----------------------------------------------
__global__ void k_u(const float* __restrict__ tra, const float* __restrict__ det) {
    __shared__ float pf[16], pm[16];
    __shared__ float sLam;
    int rr = blockIdx.x;
    const float* f;
    const float* m;
    float* u;
    if (rr < 64) { f = tra + rr * 512; m = g_m1 + rr * 512; u = g_u1 + rr * 512; }
    else         { rr -= 64; f = det + rr * 512; m = g_m2 + rr * 512; u = g_u2 + rr * 512; }
    int t = threadIdx.x;
    float fv = f[t], mv = m[t];
    float sf = warpSum(fv * fv);
    float smv = warpSum(mv * mv);
    int w = t >> 5, lane = t & 31;
    if (!lane) { pf[w] = sf; pm[w] = smv; }
    __syncthreads();
    if (t < 32) {
        float a = (t < 16) ? pf[t] : 0.f;
        float b = (t < 16) ? pm[t] : 0.f;
        a = warpSum(a);
        b = warpSum(b);
        if (!t) sLam = sqrtf(a) / sqrtf(b);
    }
    __syncthreads();
    u[t] = fv + sLam * mv;
}

// ---------------- e = relu(u @ W^T + b) : smem-tiled GEMM -------------------------
// Stacked problem: E[128][512] = U[128][512] @ W^T, U = [u1; u2].
// Tile: 32 rows x 64 cols per block, K chunks of 64 staged in smem transposed
// ([k][m] / [k][j]) so compute reads are contiguous float2/float4.
// Grid 32 = 4 m-tiles x 8 j-tiles; 256 threads; 2x4 micro-tile per thread.
__global__ void __launch_bounds__(256) k_egemm(const float* __restrict__ W,
                                               const float* __restrict__ bias) {
    __shared__ float Au[64][32];   // [k][m]
    __shared__ float Bw[64][64];   // [k][j]
    int tid = threadIdx.x;
    int mt = blockIdx.x & 3;       // 0,1 -> u1 ; 2,3 -> u2
    int jt = blockIdx.x >> 2;      // 0..7
    const float* u = (mt < 2) ? g_u1 : g_u2;
    float* e = (mt < 2) ? g_e1 : g_e2;
    int m0 = (mt & 1) * 32;
    int j0 = jt * 64;

    // loader mappings
    int lm = tid & 31, lq = tid >> 5;      // Au: row m, quad pair (lq, lq+8)
    int lj = tid & 63, q0 = (tid >> 6) * 4; // Bw: row j, quads q0..q0+3
    // compute mapping: 16x16 thread grid, 2x4 micro
    int tr = tid >> 4, tc = tid & 15;

    float acc[2][4];
#pragma unroll
    for (int i = 0; i < 2; i++)
#pragma unroll
        for (int j = 0; j < 4; j++) acc[i][j] = 0.f;

    const float* urow = u + (m0 + lm) * 512;
    const float* wrow = W + (j0 + lj) * 512;

    for (int c = 0; c < 8; c++) {
        int kc = c * 64;
        // stage Au (32m x 64k, transposed)
        {
            float4 v0 = *(const float4*)(urow + kc + 4 * lq);
            float4 v1 = *(const float4*)(urow + kc + 4 * (lq + 8));
            Au[4 * lq + 0][lm] = v0.x; Au[4 * lq + 1][lm] = v0.y;
            Au[4 * lq + 2][lm] = v0.z; Au[4 * lq + 3][lm] = v0.w;
            Au[4 * (lq + 8) + 0][lm] = v1.x; Au[4 * (lq + 8) + 1][lm] = v1.y;
            Au[4 * (lq + 8) + 2][lm] = v1.z; Au[4 * (lq + 8) + 3][lm] = v1.w;
        }
        // stage Bw (64j x 64k, transposed)
#pragma unroll
        for (int s = 0; s < 4; s++) {
            int q = q0 + s;
            float4 v = *(const float4*)(wrow + kc + 4 * q);
            Bw[4 * q + 0][lj] = v.x; Bw[4 * q + 1][lj] = v.y;
            Bw[4 * q + 2][lj] = v.z; Bw[4 * q + 3][lj] = v.w;
        }
        __syncthreads();
#pragma unroll 8
        for (int k = 0; k < 64; k++) {
            float2 a = *(const float2*)&Au[k][2 * tr];
            float4 b = *(const float4*)&Bw[k][4 * tc];
            acc[0][0] += a.x * b.x; acc[0][1] += a.x * b.y;
            acc[0][2] += a.x * b.z; acc[0][3] += a.x * b.w;
            acc[1][0] += a.y * b.x; acc[1][1] += a.y * b.y;
            acc[1][2] += a.y * b.z; acc[1][3] += a.y * b.w;
        }
        __syncthreads();
    }

    float4 bv = *(const float4*)(bias + j0 + 4 * tc);
#pragma unroll
    for (int i = 0; i < 2; i++) {
        int m = m0 + 2 * tr + i;
        float4 o;
        o.x = fmaxf(acc[i][0] + bv.x, 0.f);
        o.y = fmaxf(acc[i][1] + bv.y, 0.f);
        o.z = fmaxf(acc[i][2] + bv.z, 0.f);
        o.w = fmaxf(acc[i][3] + bv.w, 0.f);
        *(float4*)(e + m * 512 + j0 + 4 * tc) = o;
    }
}

// ---------------- row-wise L2 normalize e in place --------------------------------
__global__ void k_enorm() {
    __shared__ float pp[16];
    __shared__ float sScale;
    int rr = blockIdx.x;
    float* e = (rr < 64) ? (g_e1 + rr * 512) : (g_e2 + (rr - 64) * 512);
    int t = threadIdx.x;
    float v = e[t];
    float s = warpSum(v * v);
    if (!(t & 31)) pp[t >> 5] = s;
    __syncthreads();
    if (t < 32) {
        float a = (t < 16) ? pp[t] : 0.f;
        a = warpSum(a);
        if (!t) sScale = 1.f / fmaxf(sqrtf(a), 1e-12f);
    }
    __syncthreads();
    e[t] = v * sScale;
}

// ---------------- P[a,b] = e1[b] . e2[a] ------------------------------------------
__global__ void k_P() {
    int gw = blockIdx.x * 32 + (threadIdx.x >> 5);
    int lane = threadIdx.x & 31;
    int a = gw >> 6, b = gw & 63;
    const float* x = g_e1 + b * 512;
    const float* y = g_e2 + a * 512;
    float s = 0.f;
#pragma unroll 4
    for (int k = lane; k < 512; k += 32) s += x[k] * y[k];
    s = warpSum(s);
    if (!lane) g_P[a * 64 + b] = s;
}

// ---------------- ADMM + PCG, Woodbury precond + closed-form alpha -----------------
__global__ void __launch_bounds__(1024, 1) k_admm(float* __restrict__ out) {
    extern __shared__ float smx[];
    float* X    = smx;             // 4160 each
    float* Rr   = smx + 4160;
    float* Dd   = smx + 8320;
    float* Pm   = smx + 12480;
    float* RAd  = smx + 16640;     // 64 each
    float* CAd  = RAd + 64;
    float* RBd  = CAd + 64;
    float* CBd  = RBd + 64;
    float* RD2  = CBd + 64;
    float* RPD2 = RD2 + 64;
    float* RAr  = RPD2 + 64;
    float* CAr  = RAr + 64;
    float* RSQ  = CAr + 64;
    float* RPR  = RSQ + 64;
    float* RP   = RPR + 64;
    float* CP   = RP + 64;
    float* RX   = CP + 64;
    float* CX   = RX + 64;
    float* y2r  = CX + 64;
    float* y2c  = y2r + 64;
    float* part = y2c + 64;        // 32
    float* scal = part + 32;       // 8

    const float rho   = 100.f;
    const float sigma = 1e-3f;
    const float beta  = 3969.f + rho + sigma;
    const float binv  = 1.f / beta;
    const float b64i  = 1.f / (beta + 64.f * rho);
    const float b128i = 1.f / (beta + 128.f * rho);
    const float cRC   = (b64i - binv) * (1.f / 64.f);
    const float cT    = (b128i - 2.f * b64i + binv) * (1.f / 4096.f);

    const int tid = threadIdx.x;
    const int w = tid >> 5, lane = tid & 31;
    const int g = lane & 15, h = lane >> 4;
    const int a0 = tid >> 6, b0 = tid & 63;
    const int rc = 2 * w + h;

    int aa[4], off[4];
#pragma unroll
    for (int k = 0; k < 4; k++) { aa[k] = a0 + 16 * k; off[k] = aa[k] * LD + b0; }

    float x[4], xr[4], z1[4], y1[4], r[4], p[4], dreg[4], wp[4];
#pragma unroll
    for (int k = 0; k < 4; k++) {
        p[k] = g_P[aa[k] * 64 + b0];
        Pm[off[k]] = p[k];
        X[off[k]] = 0.f;
        x[k] = xr[k] = z1[k] = y1[k] = 0.f;
    }
    if (tid < 64) { y2r[tid] = 0.f; y2c[tid] = 0.f; RX[tid] = 0.f; CX[tid] = 0.f; }
    __syncthreads();

    // ---- init: sums over P for Woodbury ----
    {
        float sv = 0.f, sq = 0.f;
#pragma unroll
        for (int j = 0; j < 4; j++) {
            float v = Pm[rc * LD + g + 16 * j];
            sv += v; sq += v * v;
        }
        sv = dual16(sv); sq = dual16(sq);
        if (!g) { RP[rc] = sv; RSQ[rc] = sq; }
        float cv = 0.f;
#pragma unroll
        for (int j = 0; j < 4; j++) cv += Pm[(g + 16 * j) * LD + rc];
        cv = dual16(cv);
        if (!g) CP[rc] = cv;
        __syncthreads();
        if (w == 0)      { float v = warpSum(RP[lane] + RP[lane + 32]);  if (!lane) scal[5] = v; }
        else if (w == 1) { float v = warpSum(RSQ[lane] + RSQ[lane + 32]); if (!lane) scal[6] = v; }
        else if (w == 2) { float v = warpSum(RP[lane] * RP[lane] + RP[lane + 32] * RP[lane + 32]
                                           + CP[lane] * CP[lane] + CP[lane + 32] * CP[lane + 32]);
                           if (!lane) scal[7] = v; }
        __syncthreads();
    }
    const float TP = scal[5];
    const float P2 = scal[6];
    const float SRCP2 = scal[7];
    const float pBp = binv * P2 + cRC * SRCP2 + cT * TP * TP;
    const float h12v = 2.f - b128i * TP;
    const float h11v = -pBp;
    const float h22v = -4096.f * b128i;
    const float hdet = h11v * h22v - h12v * h12v;
    const float i11 = h22v / hdet, i12 = -h12v / hdet, i22 = h11v / hdet;
#pragma unroll
    for (int k = 0; k < 4; k++)
        wp[k] = binv * p[k] + cRC * (RP[aa[k]] + CP[b0]) + cT * TP;

    float TA = 0.f, TB = 0.f, D2 = 0.f, PD2 = 0.f, SA2 = 0.f, SAB = 0.f;
    float TR = 0.f, N2 = 0.f, SRC2 = 0.f, SPC = 0.f, PR = 0.f;
    float tol2 = 1e30f;
    int conv = 0;

    auto phaseD = [&]() {
        float sv = 0.f, sp = 0.f, sq = 0.f, spq = 0.f;
#pragma unroll
        for (int j = 0; j < 4; j++) {
            int o = rc * LD + g + 16 * j;
            float m = Dd[o], q = Pm[o];
            sv += m; sp += q * m; sq += m * m; spq += q * m * m;
        }
        sv = dual16(sv); sp = dual16(sp); sq = dual16(sq); spq = dual16(spq);
        if (!g) { RAd[rc] = sv; RBd[rc] = sp; RD2[rc] = sq; RPD2[rc] = spq; }
        float cv = 0.f, cp = 0.f;
#pragma unroll
        for (int j = 0; j < 4; j++) {
            int o = (g + 16 * j) * LD + rc;
            float m = Dd[o];
            cv += m; cp += Pm[o] * m;
        }
        cv = dual16(cv); cp = dual16(cp);
        if (!g) { CAd[rc] = cv; CBd[rc] = cp; }
        __syncthreads();
        if (w == 0)      { float v = warpSum(RAd[lane] + RAd[lane + 32]);  if (!lane) scal[0] = v; }
        else if (w == 1) { float v = warpSum(RBd[lane] + RBd[lane + 32]);  if (!lane) scal[1] = v; }
        else if (w == 2) { float v = warpSum(RD2[lane] + RD2[lane + 32]);  if (!lane) scal[2] = v; }
        else if (w == 3) { float v = warpSum(RPD2[lane] + RPD2[lane + 32]); if (!lane) scal[3] = v; }
        else if (w == 4) { float v = warpSum(RAd[lane] * RAd[lane] + RAd[lane + 32] * RAd[lane + 32]
                                           + CAd[lane] * CAd[lane] + CAd[lane + 32] * CAd[lane + 32]);
                           if (!lane) scal[4] = v; }
        else if (w == 5) { float v = warpSum(RAd[lane] * RBd[lane] + RAd[lane + 32] * RBd[lane + 32]
                                           + CAd[lane] * CBd[lane] + CAd[lane + 32] * CBd[lane + 32]);
                           if (!lane) scal[5] = v; }
        __syncthreads();
        TA = scal[0]; TB = scal[1]; D2 = scal[2]; PD2 = scal[3]; SA2 = scal[4]; SAB = scal[5];
    };

    auto phaseR = [&]() {
        float sv = 0.f, sq = 0.f, pv = 0.f;
#pragma unroll
        for (int j = 0; j < 4; j++) {
            int o = rc * LD + g + 16 * j;
            float v = Rr[o];
            sv += v; sq += v * v; pv += Pm[o] * v;
        }
        sv = dual16(sv); sq = dual16(sq); pv = dual16(pv);
        if (!g) { RAr[rc] = sv; RSQ[rc] = sq; RPR[rc] = pv; }
        float cv = 0.f;
#pragma unroll
        for (int j = 0; j < 4; j++) cv += Rr[(g + 16 * j) * LD + rc];
        cv = dual16(cv);
        if (!g) CAr[rc] = cv;
        __syncthreads();
        if (w == 0)      { float v = warpSum(RAr[lane] + RAr[lane + 32]); if (!lane) scal[0] = v; }
        else if (w == 1) { float v = warpSum(RSQ[lane] + RSQ[lane + 32]); if (!lane) scal[1] = v; }
        else if (w == 2) { float v = warpSum(RAr[lane] * RAr[lane] + RAr[lane + 32] * RAr[lane + 32]
                                           + CAr[lane] * CAr[lane] + CAr[lane + 32] * CAr[lane + 32]);
                           if (!lane) scal[2] = v; }
        else if (w == 3) { float v = warpSum(RP[lane] * RAr[lane] + RP[lane + 32] * RAr[lane + 32]
                                           + CP[lane] * CAr[lane] + CP[lane + 32] * CAr[lane + 32]);
                           if (!lane) scal[3] = v; }
        else if (w == 4) { float v = warpSum(RPR[lane] + RPR[lane + 32]); if (!lane) scal[4] = v; }
        __syncthreads();
        TR = scal[0]; N2 = scal[1]; SRC2 = scal[2]; SPC = scal[3]; PR = scal[4];
    };

    auto applyK = [&](float d, float pp, int a) -> float {
        float Ra = RAd[a], Cb = CAd[b0], Rb = RBd[a], Cv = CBd[b0];
        return beta * d + rho * (Ra + Cb)
             - 0.5f * (pp * (TA - Ra - Cb + d) + (TB - Rb - Cv + pp * d));
    };

    float s1 = 0.f, s2 = 0.f, al1 = 0.f, al2 = 0.f, rhoz = 0.f;
    auto wood = [&]() {
        s1 = binv * PR + cRC * SPC + cT * TP * TR;
        s2 = b128i * TR;
        al1 = i11 * s1 + i12 * s2;
        al2 = i12 * s1 + i22 * s2;
        rhoz = binv * N2 + cRC * SRC2 + cT * TR * TR + al1 * s1 + al2 * s2;
    };

    for (int it = 0; it < 150; ++it) {
        if ((it & 7) == 0) {
            // refresh residual from scratch: publish X, strip sums, r = rhs - Kx
#pragma unroll
            for (int k = 0; k < 4; k++) X[off[k]] = x[k];
            __syncthreads();
            {
                float sv = 0.f, sp = 0.f;
#pragma unroll
                for (int j = 0; j < 4; j++) {
                    int o = rc * LD + g + 16 * j;
                    float m = X[o];
                    sv += m; sp += Pm[o] * m;
                }
                sv = dual16(sv); sp = dual16(sp);
                if (!g) { RAd[rc] = sv; RBd[rc] = sp; }
                float cv = 0.f, cp = 0.f;
#pragma unroll
                for (int j = 0; j < 4; j++) {
                    int o = (g + 16 * j) * LD + rc;
                    float m = X[o];
                    cv += m; cp += Pm[o] * m;
                }
                cv = dual16(cv); cp = dual16(cp);
                if (!g) { CAd[rc] = cv; CBd[rc] = cp; }
            }
            __syncthreads();
            TA = warpSum(RAd[lane] + RAd[lane + 32]);
            TB = warpSum(RBd[lane] + RBd[lane + 32]);
            float loc = 0.f;
#pragma unroll
            for (int k = 0; k < 4; k++) {
                float kx = applyK(x[k], p[k], aa[k]);
                float rhs = sigma * x[k] + p[k] + (rho * z1[k] - y1[k])
                          + (rho - y2c[b0]) + (rho - y2r[aa[k]]);
                r[k] = rhs - kx;
                Rr[off[k]] = r[k];
                loc += rhs * rhs;
            }
            loc = warpSum(loc);
            if (!lane) part[w] = loc;
            __syncthreads();
            float nr = warpSum(part[lane]);
            tol2 = fmaxf(nr * 1e-10f, 1e-28f);
            if (tid < 64) { RX[tid] = RAd[tid]; CX[tid] = CAd[tid]; }
            __syncthreads();
        }

        phaseR();

        if (N2 > tol2) {
            conv = 0;
            wood();
            float rho_s = rhoz;
#pragma unroll
            for (int k = 0; k < 4; k++) {
                float z = binv * r[k] + cRC * (RAr[aa[k]] + CAr[b0]) + cT * TR
                        + al1 * wp[k] + al2 * b128i;
                dreg[k] = z;
                Dd[off[k]] = z;
            }

            float prev = 3.4e38f;
            int stag = 0;
            for (int cg = 0; cg < 60; ++cg) {
                __syncthreads();
                phaseD();
                float dq = beta * D2 + rho * SA2 - (TA * TB - SAB + PD2);
                if (!(dq > 0.f)) break;
                float alpha = rho_s / dq;
#pragma unroll
                for (int k = 0; k < 4; k++) {
                    float q = applyK(dreg[k], p[k], aa[k]);
                    x[k] += alpha * dreg[k];
                    r[k] -= alpha * q;
                    Rr[off[k]] = r[k];
                }
                if (tid < 64) {
                    RX[tid] += alpha * RAd[tid];
                    CX[tid] += alpha * CAd[tid];
                }
                __syncthreads();
                phaseR();
                if (N2 <= tol2) break;
                if (N2 >= 0.99f * prev) { if (++stag >= 3) break; }
                else stag = 0;
                prev = N2;
                wood();
                float bk = rhoz / rho_s;
                rho_s = rhoz;
#pragma unroll
                for (int k = 0; k < 4; k++) {
                    float z = binv * r[k] + cRC * (RAr[aa[k]] + CAr[b0]) + cT * TR
                            + al1 * wp[k] + al2 * b128i;
                    dreg[k] = z + bk * dreg[k];
                    Dd[off[k]] = dreg[k];
                }
            }
        } else {
            if (++conv >= 6) break;       // ADMM fixed point: x frozen, stop
        }

        // z/y updates + incremental residual (RX/CX tracked, no X publish)
#pragma unroll
        for (int k = 0; k < 4; k++) {
            float z1n = fminf(fmaxf(x[k] + y1[k] * (1.f / rho), 0.f), 1e6f);
            float rinc = sigma * (x[k] - xr[k]) + rho * (2.f * z1n - z1[k] - x[k])
                       - rho * (CX[b0] - 1.f) - rho * (RX[aa[k]] - 1.f);
            y1[k] += rho * (x[k] - z1n);
            z1[k] = z1n;
            r[k] += rinc;
            Rr[off[k]] = r[k];
            xr[k] = x[k];
        }
        if (tid < 64) {
            y2c[tid] += rho * (CX[tid] - 1.f);
            y2r[tid] += rho * (RX[tid] - 1.f);
        }
        __syncthreads();
    }

    // publish final X, then column-wise softmax: out[0][j][i] = softmax_i(200*clip)
#pragma unroll
    for (int k = 0; k < 4; k++) X[off[k]] = x[k];
    __syncthreads();
#pragma unroll
    for (int rr = 0; rr < 2; rr++) {
        int c = 2 * w + rr;
        float v1 = fminf(fmaxf(X[lane * LD + c], 0.f), 1.f);
        float v2 = fminf(fmaxf(X[(lane + 32) * LD + c], 0.f), 1.f);
        float mx = warpMax(fmaxf(v1, v2));
        float e1v = expf(200.f * (v1 - mx));
        float e2v = expf(200.f * (v2 - mx));
        float s = warpSum(e1v + e2v);
        out[c * 64 + lane] = e1v / s;
        out[c * 64 + lane + 32] = e2v / s;
    }
}

// ------------------------------------------------------------------------------------
extern "C" void kernel_launch(void* const* d_in, const int* in_sizes, int n_in,
                              void* d_out, int out_size) {
    const float* tra = (const float*)d_in[0];   // (64,512)
    const float* det = (const float*)d_in[1];   // (64,512)
    const float* iou = (const float*)d_in[2];   // (64,64)
    const float* W   = (const float*)d_in[3];   // (512,512)
    const float* b   = (const float*)d_in[4];   // (512,)
    float* out = (float*)d_out;                 // (1,64,64)

    const int SMEM_BYTES = (16640 + 16 * 64 + 32 + 8) * 4;  // 70816
    cudaFuncSetAttribute(k_admm, cudaFuncAttributeMaxDynamicSharedMemorySize, SMEM_BYTES);

    k_mp0<<<128, 1024>>>(tra, det, iou);
    k_m12<<<64, 1024>>>(tra, det);
    k_u<<<128, 512>>>(tra, det);
    k_egemm<<<32, 256>>>(W, b);
    k_enorm<<<128, 512>>>();
    k_P<<<128, 1024>>>();
    k_admm<<<1, 1024, SMEM_BYTES>>>(out);
}

// round 11
// speedup vs baseline: 5.3860x; 5.3860x over previous
#include <cuda_runtime.h>
#include <math.h>

#define LD 65  // padded row stride for 64x64 tiles in smem

// ---------------- intermediates (device globals; no allocation allowed) -----------
__device__ float g_Mp0[64 * 64];
__device__ float g_m1[64 * 512];
__device__ float g_m2[64 * 512];
__device__ float g_u1[64 * 512];
__device__ float g_u2[64 * 512];
__device__ float g_e1[64 * 512];
__device__ float g_e2[64 * 512];
__device__ float g_P[64 * 64];   // P[a,b] = e1[b] . e2[a]

__device__ __forceinline__ float warpSum(float v) {
#pragma unroll
    for (int o = 16; o; o >>= 1) v += __shfl_xor_sync(0xffffffffu, v, o);
    return v;
}
__device__ __forceinline__ float warpMax(float v) {
#pragma unroll
    for (int o = 16; o; o >>= 1) v = fmaxf(v, __shfl_xor_sync(0xffffffffu, v, o));
    return v;
}
__device__ __forceinline__ float dual16(float v) {
#pragma unroll
    for (int o = 8; o; o >>= 1) v += __shfl_xor_sync(0xffffffffu, v, o);
    return v;
}

// ---------------- Mp0 = feat_tra @ feat_det^T + iou : warp per output -------------
__global__ void k_mp0(const float* __restrict__ tra, const float* __restrict__ det,
                      const float* __restrict__ iou) {
    int gw = blockIdx.x * 32 + (threadIdx.x >> 5);
    int lane = threadIdx.x & 31;
    int i = gw >> 6, j = gw & 63;
    const float* a = tra + i * 512;
    const float* b = det + j * 512;
    float s = 0.f;
#pragma unroll 4
    for (int k = lane; k < 512; k += 32) s += a[k] * b[k];
    s = warpSum(s);
    if (!lane) g_Mp0[i * 64 + j] = s + iou[i * 64 + j];
}

// ---------------- m1 = Mp0 @ det, m2 = Mp0^T @ tra --------------------------------
__global__ void k_m12(const float* __restrict__ tra, const float* __restrict__ det) {
    int t = blockIdx.x * blockDim.x + threadIdx.x;
    if (t < 32768) {
        int i = t >> 9, k = t & 511;
        float s = 0.f;
#pragma unroll 8
        for (int j = 0; j < 64; j++) s += g_Mp0[i * 64 + j] * det[j * 512 + k];
        g_m1[t] = s;
    } else {
        int t2 = t - 32768;
        int j = t2 >> 9, k = t2 & 511;
        float s = 0.f;
#pragma unroll 8
        for (int i = 0; i < 64; i++) s += g_Mp0[i * 64 + j] * tra[i * 512 + k];
        g_m2[t2] = s;
    }
}

// ---------------- u = feat + lam * m ----------------------------------------------
__global__ void k_u(const float* __restrict__ tra, const float* __restrict__ det) {
    __shared__ float pf[16], pm[16];
    __shared__ float sLam;
    int rr = blockIdx.x;
    const float* f;
    const float* m;
    float* u;
    if (rr < 64) { f = tra + rr * 512; m = g_m1 + rr * 512; u = g_u1 + rr * 512; }
    else         { rr -= 64; f = det + rr * 512; m = g_m2 + rr * 512; u = g_u2 + rr * 512; }
    int t = threadIdx.x;
    float fv = f[t], mv = m[t];
    float sf = warpSum(fv * fv);
    float smv = warpSum(mv * mv);
    int w = t >> 5, lane = t & 31;
    if (!lane) { pf[w] = sf; pm[w] = smv; }
    __syncthreads();
    if (t < 32) {
        float a = (t < 16) ? pf[t] : 0.f;
        float b = (t < 16) ? pm[t] : 0.f;
        a = warpSum(a);
        b = warpSum(b);
        if (!t) sLam = sqrtf(a) / sqrtf(b);
    }
    __syncthreads();
    u[t] = fv + sLam * mv;
}

// ---------------- e = relu(u @ W^T + b) : warp per output -------------------------
__global__ void k_egemm(const float* __restrict__ W, const float* __restrict__ bias) {
    int gw = blockIdx.x * 32 + (threadIdx.x >> 5);
    int lane = threadIdx.x & 31;
    int tensor = gw >> 15;
    int loc = gw & 32767;
    int i = loc >> 9, j = loc & 511;
    const float* u = (tensor ? g_u2 : g_u1) + i * 512;
    const float* wv = W + j * 512;
    float s = 0.f;
#pragma unroll 4
    for (int k = lane; k < 512; k += 32) s += u[k] * wv[k];
    s = warpSum(s);
    if (!lane) {
        float v = fmaxf(s + bias[j], 0.f);
        (tensor ? g_e2 : g_e1)[i * 512 + j] = v;
    }
}

// ---------------- row-wise L2 normalize e in place --------------------------------
__global__ void k_enorm() {
    __shared__ float pp[16];
    __shared__ float sScale;
    int rr = blockIdx.x;
    float* e = (rr < 64) ? (g_e1 + rr * 512) : (g_e2 + (rr - 64) * 512);
    int t = threadIdx.x;
    float v = e[t];
    float s = warpSum(v * v);
    if (!(t & 31)) pp[t >> 5] = s;
    __syncthreads();
    if (t < 32) {
        float a = (t < 16) ? pp[t] : 0.f;
        a = warpSum(a);
        if (!t) sScale = 1.f / fmaxf(sqrtf(a), 1e-12f);
    }
    __syncthreads();
    e[t] = v * sScale;
}

// ---------------- P[a,b] = e1[b] . e2[a] ------------------------------------------
__global__ void k_P() {
    int gw = blockIdx.x * 32 + (threadIdx.x >> 5);
    int lane = threadIdx.x & 31;
    int a = gw >> 6, b = gw & 63;
    const float* x = g_e1 + b * 512;
    const float* y = g_e2 + a * 512;
    float s = 0.f;
#pragma unroll 4
    for (int k = lane; k < 512; k += 32) s += x[k] * y[k];
    s = warpSum(s);
    if (!lane) g_P[a * 64 + b] = s;
}

// ---------------- ADMM + PCG, Woodbury precond + closed-form alpha -----------------
// Termination: (a) CG skip when N2<=tol2 for 6 outers, OR (b) x-stagnation:
// |x - x_prev|^2 <= 1e-10 |x|^2 for 3 consecutive outers (robust to FP trajectory).
__global__ void __launch_bounds__(1024, 1) k_admm(float* __restrict__ out) {
    extern __shared__ float smx[];
    float* X    = smx;             // 4160 each
    float* Rr   = smx + 4160;
    float* Dd   = smx + 8320;
    float* Pm   = smx + 12480;
    float* RAd  = smx + 16640;     // 64 each
    float* CAd  = RAd + 64;
    float* RBd  = CAd + 64;
    float* CBd  = RBd + 64;
    float* RD2  = CBd + 64;
    float* RPD2 = RD2 + 64;
    float* RAr  = RPD2 + 64;
    float* CAr  = RAr + 64;
    float* RSQ  = CAr + 64;
    float* RPR  = RSQ + 64;
    float* RP   = RPR + 64;
    float* CP   = RP + 64;
    float* RX   = CP + 64;
    float* CX   = RX + 64;
    float* y2r  = CX + 64;
    float* y2c  = y2r + 64;
    float* part = y2c + 64;        // 32
    float* prt2 = part + 32;       // 32
    float* scal = prt2 + 32;       // 8

    const float rho   = 100.f;
    const float sigma = 1e-3f;
    const float beta  = 3969.f + rho + sigma;
    const float binv  = 1.f / beta;
    const float b64i  = 1.f / (beta + 64.f * rho);
    const float b128i = 1.f / (beta + 128.f * rho);
    const float cRC   = (b64i - binv) * (1.f / 64.f);
    const float cT    = (b128i - 2.f * b64i + binv) * (1.f / 4096.f);

    const int tid = threadIdx.x;
    const int w = tid >> 5, lane = tid & 31;
    const int g = lane & 15, h = lane >> 4;
    const int a0 = tid >> 6, b0 = tid & 63;
    const int rc = 2 * w + h;

    int aa[4], off[4];
#pragma unroll
    for (int k = 0; k < 4; k++) { aa[k] = a0 + 16 * k; off[k] = aa[k] * LD + b0; }

    float x[4], xr[4], z1[4], y1[4], r[4], p[4], dreg[4], wp[4];
#pragma unroll
    for (int k = 0; k < 4; k++) {
        p[k] = g_P[aa[k] * 64 + b0];
        Pm[off[k]] = p[k];
        X[off[k]] = 0.f;
        x[k] = xr[k] = z1[k] = y1[k] = 0.f;
    }
    if (tid < 64) { y2r[tid] = 0.f; y2c[tid] = 0.f; RX[tid] = 0.f; CX[tid] = 0.f; }
    __syncthreads();

    // ---- init: sums over P for Woodbury ----
    {
        float sv = 0.f, sq = 0.f;
#pragma unroll
        for (int j = 0; j < 4; j++) {
            float v = Pm[rc * LD + g + 16 * j];
            sv += v; sq += v * v;
        }
        sv = dual16(sv); sq = dual16(sq);
        if (!g) { RP[rc] = sv; RSQ[rc] = sq; }
        float cv = 0.f;
#pragma unroll
        for (int j = 0; j < 4; j++) cv += Pm[(g + 16 * j) * LD + rc];
        cv = dual16(cv);
        if (!g) CP[rc] = cv;
        __syncthreads();
        if (w == 0)      { float v = warpSum(RP[lane] + RP[lane + 32]);  if (!lane) scal[5] = v; }
        else if (w == 1) { float v = warpSum(RSQ[lane] + RSQ[lane + 32]); if (!lane) scal[6] = v; }
        else if (w == 2) { float v = warpSum(RP[lane] * RP[lane] + RP[lane + 32] * RP[lane + 32]
                                           + CP[lane] * CP[lane] + CP[lane + 32] * CP[lane + 32]);
                           if (!lane) scal[7] = v; }
        __syncthreads();
    }
    const float TP = scal[5];
    const float P2 = scal[6];
    const float SRCP2 = scal[7];
    const float pBp = binv * P2 + cRC * SRCP2 + cT * TP * TP;
    const float h12v = 2.f - b128i * TP;
    const float h11v = -pBp;
    const float h22v = -4096.f * b128i;
    const float hdet = h11v * h22v - h12v * h12v;
    const float i11 = h22v / hdet, i12 = -h12v / hdet, i22 = h11v / hdet;
#pragma unroll
    for (int k = 0; k < 4; k++)
        wp[k] = binv * p[k] + cRC * (RP[aa[k]] + CP[b0]) + cT * TP;

    float TA = 0.f, TB = 0.f, D2 = 0.f, PD2 = 0.f, SA2 = 0.f, SAB = 0.f;
    float TR = 0.f, N2 = 0.f, SRC2 = 0.f, SPC = 0.f, PR = 0.f;
    float tol2 = 1e30f;
    int conv = 0, convS = 0;

    auto phaseD = [&]() {
        float sv = 0.f, sp = 0.f, sq = 0.f, spq = 0.f;
#pragma unroll
        for (int j = 0; j < 4; j++) {
            int o = rc * LD + g + 16 * j;
            float m = Dd[o], q = Pm[o];
            sv += m; sp += q * m; sq += m * m; spq += q * m * m;
        }
        sv = dual16(sv); sp = dual16(sp); sq = dual16(sq); spq = dual16(spq);
        if (!g) { RAd[rc] = sv; RBd[rc] = sp; RD2[rc] = sq; RPD2[rc] = spq; }
        float cv = 0.f, cp = 0.f;
#pragma unroll
        for (int j = 0; j < 4; j++) {
            int o = (g + 16 * j) * LD + rc;
            float m = Dd[o];
            cv += m; cp += Pm[o] * m;
        }
        cv = dual16(cv); cp = dual16(cp);
        if (!g) { CAd[rc] = cv; CBd[rc] = cp; }
        __syncthreads();
        if (w == 0)      { float v = warpSum(RAd[lane] + RAd[lane + 32]);  if (!lane) scal[0] = v; }
        else if (w == 1) { float v = warpSum(RBd[lane] + RBd[lane + 32]);  if (!lane) scal[1] = v; }
        else if (w == 2) { float v = warpSum(RD2[lane] + RD2[lane + 32]);  if (!lane) scal[2] = v; }
        else if (w == 3) { float v = warpSum(RPD2[lane] + RPD2[lane + 32]); if (!lane) scal[3] = v; }
        else if (w == 4) { float v = warpSum(RAd[lane] * RAd[lane] + RAd[lane + 32] * RAd[lane + 32]
                                           + CAd[lane] * CAd[lane] + CAd[lane + 32] * CAd[lane + 32]);
                           if (!lane) scal[4] = v; }
        else if (w == 5) { float v = warpSum(RAd[lane] * RBd[lane] + RAd[lane + 32] * RBd[lane + 32]
                                           + CAd[lane] * CBd[lane] + CAd[lane + 32] * CBd[lane + 32]);
                           if (!lane) scal[5] = v; }
        __syncthreads();
        TA = scal[0]; TB = scal[1]; D2 = scal[2]; PD2 = scal[3]; SA2 = scal[4]; SAB = scal[5];
    };

    auto phaseR = [&]() {
        float sv = 0.f, sq = 0.f, pv = 0.f;
#pragma unroll
        for (int j = 0; j < 4; j++) {
            int o = rc * LD + g + 16 * j;
            float v = Rr[o];
            sv += v; sq += v * v; pv += Pm[o] * v;
        }
        sv = dual16(sv); sq = dual16(sq); pv = dual16(pv);
        if (!g) { RAr[rc] = sv; RSQ[rc] = sq; RPR[rc] = pv; }
        float cv = 0.f;
#pragma unroll
        for (int j = 0; j < 4; j++) cv += Rr[(g + 16 * j) * LD + rc];
        cv = dual16(cv);
        if (!g) CAr[rc] = cv;
        __syncthreads();
        if (w == 0)      { float v = warpSum(RAr[lane] + RAr[lane + 32]); if (!lane) scal[0] = v; }
        else if (w == 1) { float v = warpSum(RSQ[lane] + RSQ[lane + 32]); if (!lane) scal[1] = v; }
        else if (w == 2) { float v = warpSum(RAr[lane] * RAr[lane] + RAr[lane + 32] * RAr[lane + 32]
                                           + CAr[lane] * CAr[lane] + CAr[lane + 32] * CAr[lane + 32]);
                           if (!lane) scal[2] = v; }
        else if (w == 3) { float v = warpSum(RP[lane] * RAr[lane] + RP[lane + 32] * RAr[lane + 32]
                                           + CP[lane] * CAr[lane] + CP[lane + 32] * CAr[lane + 32]);
                           if (!lane) scal[3] = v; }
        else if (w == 4) { float v = warpSum(RPR[lane] + RPR[lane + 32]); if (!lane) scal[4] = v; }
        __syncthreads();
        TR = scal[0]; N2 = scal[1]; SRC2 = scal[2]; SPC = scal[3]; PR = scal[4];
    };

    auto applyK = [&](float d, float pp, int a) -> float {
        float Ra = RAd[a], Cb = CAd[b0], Rb = RBd[a], Cv = CBd[b0];
        return beta * d + rho * (Ra + Cb)
             - 0.5f * (pp * (TA - Ra - Cb + d) + (TB - Rb - Cv + pp * d));
    };

    float s1 = 0.f, s2 = 0.f, al1 = 0.f, al2 = 0.f, rhoz = 0.f;
    auto wood = [&]() {
        s1 = binv * PR + cRC * SPC + cT * TP * TR;
        s2 = b128i * TR;
        al1 = i11 * s1 + i12 * s2;
        al2 = i12 * s1 + i22 * s2;
        rhoz = binv * N2 + cRC * SRC2 + cT * TR * TR + al1 * s1 + al2 * s2;
    };

    for (int it = 0; it < 150; ++it) {
        if ((it & 7) == 0) {
            // refresh residual from scratch: publish X, strip sums, r = rhs - Kx
#pragma unroll
            for (int k = 0; k < 4; k++) X[off[k]] = x[k];
            __syncthreads();
            {
                float sv = 0.f, sp = 0.f;
#pragma unroll
                for (int j = 0; j < 4; j++) {
                    int o = rc * LD + g + 16 * j;
                    float m = X[o];
                    sv += m; sp += Pm[o] * m;
                }
                sv = dual16(sv); sp = dual16(sp);
                if (!g) { RAd[rc] = sv; RBd[rc] = sp; }
                float cv = 0.f, cp = 0.f;
#pragma unroll
                for (int j = 0; j < 4; j++) {
                    int o = (g + 16 * j) * LD + rc;
                    float m = X[o];
                    cv += m; cp += Pm[o] * m;
                }
                cv = dual16(cv); cp = dual16(cp);
                if (!g) { CAd[rc] = cv; CBd[rc] = cp; }
            }
            __syncthreads();
            TA = warpSum(RAd[lane] + RAd[lane + 32]);
            TB = warpSum(RBd[lane] + RBd[lane + 32]);
            float loc = 0.f;
#pragma unroll
            for (int k = 0; k < 4; k++) {
                float kx = applyK(x[k], p[k], aa[k]);
                float rhs = sigma * x[k] + p[k] + (rho * z1[k] - y1[k])
                          + (rho - y2c[b0]) + (rho - y2r[aa[k]]);
                r[k] = rhs - kx;
                Rr[off[k]] = r[k];
                loc += rhs * rhs;
            }
            loc = warpSum(loc);
            if (!lane) part[w] = loc;
            __syncthreads();
            float nr = warpSum(part[lane]);
            tol2 = fmaxf(nr * 1e-10f, 1e-28f);
            if (tid < 64) { RX[tid] = RAd[tid]; CX[tid] = CAd[tid]; }
            __syncthreads();
        }

        phaseR();

        if (N2 > tol2) {
            conv = 0;
            wood();
            float rho_s = rhoz;
#pragma unroll
            for (int k = 0; k < 4; k++) {
                float z = binv * r[k] + cRC * (RAr[aa[k]] + CAr[b0]) + cT * TR
                        + al1 * wp[k] + al2 * b128i;
                dreg[k] = z;
                Dd[off[k]] = z;
            }

            float prev = 3.4e38f;
            int stag = 0;
            for (int cg = 0; cg < 60; ++cg) {
                __syncthreads();
                phaseD();
                float dq = beta * D2 + rho * SA2 - (TA * TB - SAB + PD2);
                if (!(dq > 0.f)) break;
                float alpha = rho_s / dq;
#pragma unroll
                for (int k = 0; k < 4; k++) {
                    float q = applyK(dreg[k], p[k], aa[k]);
                    x[k] += alpha * dreg[k];
                    r[k] -= alpha * q;
                    Rr[off[k]] = r[k];
                }
                if (tid < 64) {
                    RX[tid] += alpha * RAd[tid];
                    CX[tid] += alpha * CAd[tid];
                }
                __syncthreads();
                phaseR();
                if (N2 <= tol2) break;
                if (N2 >= 0.99f * prev) { if (++stag >= 3) break; }
                else stag = 0;
                prev = N2;
                wood();
                float bk = rhoz / rho_s;
                rho_s = rhoz;
#pragma unroll
                for (int k = 0; k < 4; k++) {
                    float z = binv * r[k] + cRC * (RAr[aa[k]] + CAr[b0]) + cT * TR
                            + al1 * wp[k] + al2 * b128i;
                    dreg[k] = z + bk * dreg[k];
                    Dd[off[k]] = dreg[k];
                }
            }
        } else {
            if (++conv >= 6) break;       // ADMM fixed point: x frozen, stop
        }

        // z/y updates + incremental residual; also reduce |x-xr|^2 and |x|^2
        float locD = 0.f, locX = 0.f;
#pragma unroll
        for (int k = 0; k < 4; k++) {
            float z1n = fminf(fmaxf(x[k] + y1[k] * (1.f / rho), 0.f), 1e6f);
            float dx = x[k] - xr[k];
            float rinc = sigma * dx + rho * (2.f * z1n - z1[k] - x[k])
                       - rho * (CX[b0] - 1.f) - rho * (RX[aa[k]] - 1.f);
            y1[k] += rho * (x[k] - z1n);
            z1[k] = z1n;
            r[k] += rinc;
            Rr[off[k]] = r[k];
            xr[k] = x[k];
            locD += dx * dx;
            locX += x[k] * x[k];
        }
        locD = warpSum(locD);
        locX = warpSum(locX);
        if (!lane) { part[w] = locD; prt2[w] = locX; }
        if (tid < 64) {
            y2c[tid] += rho * (CX[tid] - 1.f);
            y2r[tid] += rho * (RX[tid] - 1.f);
        }
        __syncthreads();
        float delta2 = warpSum(part[lane]);
        float x2 = warpSum(prt2[lane]);
        if (delta2 <= 1e-10f * x2 + 1e-30f) {
            if (++convS >= 3) break;      // x stagnant 3 outers: converged
        } else convS = 0;
    }

    // publish final X, then column-wise softmax: out[0][j][i] = softmax_i(200*clip)
#pragma unroll
    for (int k = 0; k < 4; k++) X[off[k]] = x[k];
    __syncthreads();
#pragma unroll
    for (int rr = 0; rr < 2; rr++) {
        int c = 2 * w + rr;
        float v1 = fminf(fmaxf(X[lane * LD + c], 0.f), 1.f);
        float v2 = fminf(fmaxf(X[(lane + 32) * LD + c], 0.f), 1.f);
        float mx = warpMax(fmaxf(v1, v2));
        float e1v = expf(200.f * (v1 - mx));
        float e2v = expf(200.f * (v2 - mx));
        float s = warpSum(e1v + e2v);
        out[c * 64 + lane] = e1v / s;
        out[c * 64 + lane + 32] = e2v / s;
    }
}

// ------------------------------------------------------------------------------------
extern "C" void kernel_launch(void* const* d_in, const int* in_sizes, int n_in,
                              void* d_out, int out_size) {
    const float* tra = (const float*)d_in[0];   // (64,512)
    const float* det = (const float*)d_in[1];   // (64,512)
    const float* iou = (const float*)d_in[2];   // (64,64)
    const float* W   = (const float*)d_in[3];   // (512,512)
    const float* b   = (const float*)d_in[4];   // (512,)
    float* out = (float*)d_out;                 // (1,64,64)

    const int SMEM_BYTES = (16640 + 16 * 64 + 64 + 8) * 4;  // 70944
    cudaFuncSetAttribute(k_admm, cudaFuncAttributeMaxDynamicSharedMemorySize, SMEM_BYTES);

    k_mp0<<<128, 1024>>>(tra, det, iou);
    k_m12<<<64, 1024>>>(tra, det);
    k_u<<<128, 512>>>(tra, det);
    k_egemm<<<2048, 1024>>>(W, b);
    k_enorm<<<128, 512>>>();
    k_P<<<128, 1024>>>();
    k_admm<<<1, 1024, SMEM_BYTES>>>(out);
}